// round 1
// baseline (speedup 1.0000x reference)
#include <cuda_runtime.h>
#include <stdint.h>

// PureAEVComputer radial AEV: B=4, N=1024, 4 species x 16 shells, out width 1008.
// species: (B,N) int32 or int64 (detected at runtime), coordinates: (B,N,3) f32.

#define NB 4
#define NN 1024
#define PAD 1152          // 1024 + 4*31 rounded up to 32-multiple
#define OUTW 1008
#define RC2 27.04f        // 5.2^2
#define PI_OVER_RC 0.6041524333826525f
#define CC (-23.083120654223414f)   // -16 * log2(e)

__device__ int    g_is64;
__device__ float4 g_sorted[NB * PAD];
__device__ int    g_ps[NB * 5];     // padded segment starts per batch (5 boundaries)

// ---------------------------------------------------------------------------
// Kernel 1: detect whether species buffer is int64 or int32.
// Inspect first 1024 elements (2048 int32 words: safe under both layouts).
// int64 little-endian => every odd word is 0 and even words are in [0,4).
// ---------------------------------------------------------------------------
__global__ void detect_kernel(const int* __restrict__ w) {
    __shared__ int bad;
    if (threadIdx.x == 0) bad = 0;
    __syncthreads();
    int v = 0;
    for (int e = threadIdx.x; e < NN; e += 256) {
        int lo = w[2 * e];
        int hi = w[2 * e + 1];
        if (hi != 0 || ((unsigned)lo) > 3u) v = 1;
    }
    if (v) atomicOr(&bad, 1);
    __syncthreads();
    if (threadIdx.x == 0) g_is64 = bad ? 0 : 1;
}

// ---------------------------------------------------------------------------
// Kernel 2: per-batch counting sort of neighbor atoms by species.
// Builds g_sorted[b]: 4 segments (padded to 32-multiples) of float4 coords,
// padding filled with far-away sentinels (contribute exactly 0).
// Warp 0 does count + scatter (ballot-based, no atomics); other threads fill
// sentinels.
// ---------------------------------------------------------------------------
__global__ void sort_kernel(const int* __restrict__ spw,
                            const float* __restrict__ coords) {
    int b = blockIdx.x;
    int tid = threadIdx.x;

    // sentinel fill
    for (int t = tid; t < PAD; t += 256)
        g_sorted[b * PAD + t] = make_float4(1e9f, 1e9f, 1e9f, 0.f);
    __syncthreads();

    if (tid < 32) {
        const int is64 = g_is64;
        const unsigned full = 0xffffffffu;
        const unsigned lt = (1u << tid) - 1u;

        // pass 1: count
        int c0 = 0, c1 = 0, c2 = 0, c3 = 0;
        for (int it = 0; it < NN / 32; ++it) {
            int e = it * 32 + tid;
            int sp = is64 ? spw[2 * (b * NN + e)] : spw[b * NN + e];
            bool ok = ((unsigned)sp) <= 3u;
            c0 += __popc(__ballot_sync(full, ok && sp == 0));
            c1 += __popc(__ballot_sync(full, ok && sp == 1));
            c2 += __popc(__ballot_sync(full, ok && sp == 2));
            c3 += __popc(__ballot_sync(full, ok && sp == 3));
        }
        int p0 = ((c0 + 31) >> 5) << 5;
        int p1 = ((c1 + 31) >> 5) << 5;
        int p2 = ((c2 + 31) >> 5) << 5;
        int p3 = ((c3 + 31) >> 5) << 5;
        int s0 = 0, s1 = p0, s2 = p0 + p1, s3 = p0 + p1 + p2;
        if (tid == 0) {
            g_ps[b * 5 + 0] = s0;
            g_ps[b * 5 + 1] = s1;
            g_ps[b * 5 + 2] = s2;
            g_ps[b * 5 + 3] = s3;
            g_ps[b * 5 + 4] = s3 + p3;
        }

        // pass 2: scatter
        int u0 = 0, u1 = 0, u2 = 0, u3 = 0;
        for (int it = 0; it < NN / 32; ++it) {
            int e = it * 32 + tid;
            int sp = is64 ? spw[2 * (b * NN + e)] : spw[b * NN + e];
            bool ok = ((unsigned)sp) <= 3u;
            unsigned m0 = __ballot_sync(full, ok && sp == 0);
            unsigned m1 = __ballot_sync(full, ok && sp == 1);
            unsigned m2 = __ballot_sync(full, ok && sp == 2);
            unsigned m3 = __ballot_sync(full, ok && sp == 3);
            if (ok) {
                int base, rank;
                if (sp == 0)      { base = s0 + u0; rank = __popc(m0 & lt); }
                else if (sp == 1) { base = s1 + u1; rank = __popc(m1 & lt); }
                else if (sp == 2) { base = s2 + u2; rank = __popc(m2 & lt); }
                else              { base = s3 + u3; rank = __popc(m3 & lt); }
                const float* cp = coords + ((size_t)(b * NN + e)) * 3;
                g_sorted[b * PAD + base + rank] =
                    make_float4(cp[0], cp[1], cp[2], 0.f);
            }
            u0 += __popc(m0); u1 += __popc(m1);
            u2 += __popc(m2); u3 += __popc(m3);
        }
    }
}

// ---------------------------------------------------------------------------
// Kernel 3: main AEV compute. One warp per output row (b,i); 8 warps/block,
// all rows in a block share batch b; sorted coords staged in smem.
// exp(-16(d-s_k)^2) = exp2( CC*d^2 + A_k*d + B_k ), A_k = -2*CC*s_k (imm FFMA),
// B_k = CC*s_k^2.
// ---------------------------------------------------------------------------
__global__ void __launch_bounds__(256)
aev_kernel(const float* __restrict__ coords, float* __restrict__ out) {
    __shared__ float4 sco[PAD];
    __shared__ int sps[5];

    const int tid = threadIdx.x;
    const int b = blockIdx.x >> 7;              // 128 blocks per batch
    for (int t = tid; t < PAD; t += 256)
        sco[t] = g_sorted[b * PAD + t];
    if (tid < 5) sps[tid] = g_ps[b * 5 + tid];
    __syncthreads();

    const int w = tid >> 5;
    const int lane = tid & 31;
    const int i = ((blockIdx.x & 127) << 3) + w;

    const float* cc = coords + ((size_t)(b * NN + i)) * 3;
    const float xi = cc[0], yi = cc[1], zi = cc[2];

    float* orow = out + (size_t)(b * NN + i) * OUTW;
    float4* o4 = (float4*)orow;

    // zero the padded tail: floats [64,1008) == float4 [16,252)
    const float4 z4 = make_float4(0.f, 0.f, 0.f, 0.f);
    for (int c = 16 + lane; c < 252; c += 32) o4[c] = z4;

    const float SHF[16] = {0.9f, 1.16875f, 1.4375f, 1.70625f, 1.975f, 2.24375f,
                           2.5125f, 2.78125f, 3.05f, 3.31875f, 3.5875f,
                           3.85625f, 4.125f, 4.39375f, 4.6625f, 4.93125f};

    for (int s = 0; s < 4; ++s) {
        float acc[16];
#pragma unroll
        for (int k = 0; k < 16; ++k) acc[k] = 0.f;

        const int en = sps[s + 1];
        for (int t = sps[s] + lane; t < en; t += 32) {
            float4 cj = sco[t];
            float dx = xi - cj.x, dy = yi - cj.y, dz = zi - cj.z;
            float d2 = fmaf(dx, dx, fmaf(dy, dy, dz * dz));
            bool okin = (d2 > 0.f) && (d2 <= RC2);
            float d = d2 * rsqrtf(d2);          // NaN at d2==0, selected away
            float fcv = fmaf(0.5f, __cosf(d * PI_OVER_RC), 0.5f);
            float fc = okin ? fcv : 0.f;
            float ds = okin ? d : 1e9f;         // consistent sentinel pair:
            float d2s = okin ? d2 : 1e18f;      // exp2 arg -> -2.3e19 -> 0
            float base = CC * d2s;
#pragma unroll
            for (int k = 0; k < 16; ++k) {
                float sh = SHF[k];
                float A = -2.0f * CC * sh;      // immediate multiplier
                float Bc = CC * sh * sh;
                float g = exp2f(base + fmaf(A, ds, Bc));
                acc[k] = fmaf(fc, g, acc[k]);
            }
        }

#pragma unroll
        for (int k = 0; k < 16; ++k) {
#pragma unroll
            for (int off = 16; off; off >>= 1)
                acc[k] += __shfl_xor_sync(0xffffffffu, acc[k], off);
        }
        if (lane == 0) {
            o4[s * 4 + 0] = make_float4(acc[0],  acc[1],  acc[2],  acc[3]);
            o4[s * 4 + 1] = make_float4(acc[4],  acc[5],  acc[6],  acc[7]);
            o4[s * 4 + 2] = make_float4(acc[8],  acc[9],  acc[10], acc[11]);
            o4[s * 4 + 3] = make_float4(acc[12], acc[13], acc[14], acc[15]);
        }
    }
}

// ---------------------------------------------------------------------------
extern "C" void kernel_launch(void* const* d_in, const int* in_sizes, int n_in,
                              void* d_out, int out_size) {
    (void)in_sizes; (void)n_in; (void)out_size;
    const int*   spec   = (const int*)d_in[0];
    const float* coords = (const float*)d_in[1];
    float*       out    = (float*)d_out;

    detect_kernel<<<1, 256>>>(spec);
    sort_kernel<<<NB, 256>>>(spec, coords);
    aev_kernel<<<NB * (NN / 8), 256>>>(coords, out);
}

// round 2
// speedup vs baseline: 1.8110x; 1.8110x over previous
#include <cuda_runtime.h>
#include <stdint.h>

// PureAEVComputer radial AEV, fully fused single kernel.
// B=4, N=1024, 4 species x 16 shells, out width 1008 (tail zero).
// species: (B,N) int32 or int64 (runtime-detected); coords: (B,N,3) f32.

#define NB 4
#define NN 1024
#define PAD 1152                      // max padded total: 1024 + 4*31 -> 1148
#define OUTW 1008
#define RC2 27.04f                    // 5.2^2
#define PI_OVER_RC 0.6041524334f
#define LLC 23.083120654223414f       // eta * log2(e), eta=16
#define KP  12.407177351644683f       // 2 * LLC * 0.26875
#define LD  6.2035886758223416f       // LLC * 0.26875

__global__ void __launch_bounds__(128)
aev_fused(const int* __restrict__ spw, const float* __restrict__ coords,
          float* __restrict__ out) {
    __shared__ float4 sco[PAD];
    __shared__ int    ssp[NN];
    __shared__ int    wcnt[4][4];
    __shared__ int    woff[4][4];
    __shared__ int    sbase[5];
    __shared__ int    sbad;

    const int tid  = threadIdx.x;
    const int w    = tid >> 5;
    const int lane = tid & 31;
    const int b    = blockIdx.x >> 8;          // 256 blocks per batch
    const unsigned full = 0xffffffffu;

    if (tid == 0) sbad = 0;
    // sentinel fill (independent of sbad init ordering w.r.t. other threads'
    // reads because everything is resolved at the next __syncthreads)
    for (int t = tid; t < PAD; t += 128)
        sco[t] = make_float4(1e9f, 1e9f, 1e9f, 0.f);
    __syncthreads();

    // ---- detect int64 vs int32 from first 512 elements (safe both ways) ----
    int bad = 0;
    for (int q = tid; q < 512; q += 128) {
        int lo = spw[2 * q], hi = spw[2 * q + 1];
        if (hi != 0 || ((unsigned)lo) > 3u) bad = 1;
    }
    if (bad) atomicOr(&sbad, 1);
    __syncthreads();
    const int is64 = !sbad;

    // ---- stage this batch's species ----
    for (int e = tid; e < NN; e += 128)
        ssp[e] = is64 ? spw[2 * (b * NN + e)] : spw[b * NN + e];
    __syncthreads();

    // ---- per-warp histogram (warp w owns elements [w*256, w*256+256)) ----
    {
        int c0 = 0, c1 = 0, c2 = 0, c3 = 0;
        for (int it = 0; it < 8; ++it) {
            int sp = ssp[w * 256 + it * 32 + lane];
            c0 += __popc(__ballot_sync(full, sp == 0));
            c1 += __popc(__ballot_sync(full, sp == 1));
            c2 += __popc(__ballot_sync(full, sp == 2));
            c3 += __popc(__ballot_sync(full, sp == 3));
        }
        if (lane == 0) {
            wcnt[w][0] = c0; wcnt[w][1] = c1; wcnt[w][2] = c2; wcnt[w][3] = c3;
        }
    }
    __syncthreads();

    // ---- segment bases (padded to 32) + per-warp scatter offsets ----
    if (tid == 0) {
        int basep = 0;
        for (int s = 0; s < 4; ++s) {
            sbase[s] = basep;
            int tot = 0;
            for (int ww = 0; ww < 4; ++ww) { woff[ww][s] = basep + tot; tot += wcnt[ww][s]; }
            basep += (tot + 31) & ~31;
        }
        sbase[4] = basep;
    }
    __syncthreads();

    // ---- scatter coords into species-sorted smem ----
    {
        const unsigned lt = (1u << lane) - 1u;
        int u0 = 0, u1 = 0, u2 = 0, u3 = 0;
        for (int it = 0; it < 8; ++it) {
            int e  = w * 256 + it * 32 + lane;
            int sp = ssp[e];
            unsigned m0 = __ballot_sync(full, sp == 0);
            unsigned m1 = __ballot_sync(full, sp == 1);
            unsigned m2 = __ballot_sync(full, sp == 2);
            unsigned m3 = __ballot_sync(full, sp == 3);
            int pos = -1;
            if (sp == 0)      pos = woff[w][0] + u0 + __popc(m0 & lt);
            else if (sp == 1) pos = woff[w][1] + u1 + __popc(m1 & lt);
            else if (sp == 2) pos = woff[w][2] + u2 + __popc(m2 & lt);
            else if (sp == 3) pos = woff[w][3] + u3 + __popc(m3 & lt);
            if (pos >= 0) {
                const float* cp = coords + (size_t)(b * NN + e) * 3;
                sco[pos] = make_float4(cp[0], cp[1], cp[2], 0.f);
            }
            u0 += __popc(m0); u1 += __popc(m1); u2 += __popc(m2); u3 += __popc(m3);
        }
    }
    __syncthreads();

    // =================== main compute: one warp per row ===================
    const int i = ((blockIdx.x & 255) << 2) + w;
    const float* cc = coords + (size_t)(b * NN + i) * 3;
    const float xi = cc[0], yi = cc[1], zi = cc[2];

    float* orow = out + (size_t)(b * NN + i) * OUTW;
    float4* o4 = (float4*)orow;
    const float4 z4 = make_float4(0.f, 0.f, 0.f, 0.f);
    for (int c = 16 + lane; c < 252; c += 32) o4[c] = z4;   // zero tail

    int sb[5];
#pragma unroll
    for (int k = 0; k < 5; ++k) sb[k] = sbase[k];

    // chain constants (14 one-time exp2f per thread; anchors at shells 3, 11)
    const float u3  = exp2f(-LD * 3.68125f);   // s3+s4
    const float u4  = exp2f(-LD * 4.21875f);   // s4+s5
    const float u5  = exp2f(-LD * 4.75625f);   // s5+s6
    const float u6  = exp2f(-LD * 5.29375f);   // s6+s7
    const float dn3 = exp2f( LD * 3.14375f);   // s2+s3
    const float dn2 = exp2f( LD * 2.60625f);   // s1+s2
    const float dn1 = exp2f( LD * 2.06875f);   // s0+s1
    const float u11 = exp2f(-LD * 7.98125f);   // s11+s12
    const float u12 = exp2f(-LD * 8.51875f);   // s12+s13
    const float u13 = exp2f(-LD * 9.05625f);   // s13+s14
    const float u14 = exp2f(-LD * 9.59375f);   // s14+s15
    const float dn11 = exp2f(LD * 7.44375f);   // s10+s11
    const float dn10 = exp2f(LD * 6.90625f);   // s9+s10
    const float dn9  = exp2f(LD * 6.36875f);   // s8+s9

#pragma unroll
    for (int s = 0; s < 4; ++s) {
        float acc[16];
#pragma unroll
        for (int k = 0; k < 16; ++k) acc[k] = 0.f;

        const int en = sb[s + 1];
        for (int t = sb[s] + lane; t < en; t += 32) {
            float4 cj = sco[t];
            float dx = xi - cj.x, dy = yi - cj.y, dz = zi - cj.z;
            float d2 = fmaf(dx, dx, fmaf(dy, dy, dz * dz));
            bool ok = (d2 > 0.f) && (d2 <= RC2);
            float dr = d2 * rsqrtf(d2);            // NaN at d2==0, selected away
            float d  = ok ? dr : 0.f;              // masked -> d=0 (finite path)
            float fcv = fmaf(0.5f, __cosf(d * PI_OVER_RC), 0.5f);
            float fc = ok ? fcv : 0.f;             // masked -> contribution 0

            // anchors: g = exp2(-LLC*(d-s)^2), folded with fc
            float fA = d - 1.70625f;               // shell 3
            float gA = exp2f((-LLC * fA) * fA);
            float fB = d - 3.85625f;               // shell 11
            float gB = exp2f((-LLC * fB) * fB);
            float P  = exp2f(KP * d);              // up-step factor
            float Q  = exp2f(-KP * d);             // down-step factor
            float hA = fc * gA;
            float hB = fc * gB;

            acc[3]  += hA;
            acc[11] += hB;
            float h;
            h = hA;  h *= P * u3;  acc[4]  += h;
                     h *= P * u4;  acc[5]  += h;
                     h *= P * u5;  acc[6]  += h;
                     h *= P * u6;  acc[7]  += h;
            h = hA;  h *= Q * dn3; acc[2]  += h;
                     h *= Q * dn2; acc[1]  += h;
                     h *= Q * dn1; acc[0]  += h;
            h = hB;  h *= P * u11; acc[12] += h;
                     h *= P * u12; acc[13] += h;
                     h *= P * u13; acc[14] += h;
                     h *= P * u14; acc[15] += h;
            h = hB;  h *= Q * dn11; acc[10] += h;
                     h *= Q * dn10; acc[9]  += h;
                     h *= Q * dn9;  acc[8]  += h;
        }

#pragma unroll
        for (int k = 0; k < 16; ++k) {
#pragma unroll
            for (int off = 16; off; off >>= 1)
                acc[k] += __shfl_xor_sync(full, acc[k], off);
        }
        if (lane == 0) {
            o4[s * 4 + 0] = make_float4(acc[0],  acc[1],  acc[2],  acc[3]);
            o4[s * 4 + 1] = make_float4(acc[4],  acc[5],  acc[6],  acc[7]);
            o4[s * 4 + 2] = make_float4(acc[8],  acc[9],  acc[10], acc[11]);
            o4[s * 4 + 3] = make_float4(acc[12], acc[13], acc[14], acc[15]);
        }
    }
}

extern "C" void kernel_launch(void* const* d_in, const int* in_sizes, int n_in,
                              void* d_out, int out_size) {
    (void)in_sizes; (void)n_in; (void)out_size;
    const int*   spec   = (const int*)d_in[0];
    const float* coords = (const float*)d_in[1];
    float*       out    = (float*)d_out;

    aev_fused<<<NB * (NN / 4), 128>>>(spec, coords, out);
}

// round 3
// speedup vs baseline: 1.9683x; 1.0869x over previous
#include <cuda_runtime.h>
#include <stdint.h>

// PureAEVComputer radial AEV, fused single kernel, anchor-chain Gaussians.
// B=4, N=1024, 4 species x 16 shells, out width 1008 (tail zero).

#define NB 4
#define NN 1024
#define PAD 1152
#define OUTW 1008
#define RC2 27.04f
#define RCF 5.2f
#define PI_OVER_RC 0.6041524334f
#define LLCF 23.083120654223414f      // eta * log2(e), eta=16
#define KPF  12.407177351645084f      // 2 * LLC * 0.26875
#define SA 1.70625f                   // anchor A = shell 3
#define SB 3.85625f                   // anchor B = shell 11
// T^(m^2) = exp2(-LLC*Delta^2*m^2), Delta=0.26875; exponent unit 1.6672144566
#define ET1  (-1.6672144566273082f)
#define ET4  (-6.6688578265092330f)
#define ET9  (-15.004930109645774f)
#define ET16 (-26.675431306036931f)

__global__ void __launch_bounds__(128)
aev_fused(const int* __restrict__ spw, const float* __restrict__ coords,
          float* __restrict__ out) {
    __shared__ float4 sco[PAD];
    __shared__ int    ssp[NN];
    __shared__ int    wcnt[4][4];
    __shared__ int    woff[4][4];
    __shared__ int    sbase[5];
    __shared__ int    sbad;

    const int tid  = threadIdx.x;
    const int w    = tid >> 5;
    const int lane = tid & 31;
    const int b    = blockIdx.x >> 8;          // 256 blocks per batch
    const unsigned full = 0xffffffffu;

    if (tid == 0) sbad = 0;
    for (int t = tid; t < PAD; t += 128)
        sco[t] = make_float4(1e9f, 1e9f, 1e9f, 0.f);
    __syncthreads();

    // ---- detect int64 vs int32 from first 512 elements ----
    int bad = 0;
    for (int q = tid; q < 512; q += 128) {
        int lo = spw[2 * q], hi = spw[2 * q + 1];
        if (hi != 0 || ((unsigned)lo) > 3u) bad = 1;
    }
    if (bad) atomicOr(&sbad, 1);
    __syncthreads();
    const int is64 = !sbad;

    for (int e = tid; e < NN; e += 128)
        ssp[e] = is64 ? spw[2 * (b * NN + e)] : spw[b * NN + e];
    __syncthreads();

    // ---- per-warp histogram ----
    {
        int c0 = 0, c1 = 0, c2 = 0, c3 = 0;
        for (int it = 0; it < 8; ++it) {
            int sp = ssp[w * 256 + it * 32 + lane];
            c0 += __popc(__ballot_sync(full, sp == 0));
            c1 += __popc(__ballot_sync(full, sp == 1));
            c2 += __popc(__ballot_sync(full, sp == 2));
            c3 += __popc(__ballot_sync(full, sp == 3));
        }
        if (lane == 0) {
            wcnt[w][0] = c0; wcnt[w][1] = c1; wcnt[w][2] = c2; wcnt[w][3] = c3;
        }
    }
    __syncthreads();

    if (tid == 0) {
        int basep = 0;
        for (int s = 0; s < 4; ++s) {
            sbase[s] = basep;
            int tot = 0;
            for (int ww = 0; ww < 4; ++ww) { woff[ww][s] = basep + tot; tot += wcnt[ww][s]; }
            basep += (tot + 31) & ~31;
        }
        sbase[4] = basep;
    }
    __syncthreads();

    // ---- scatter coords into species-sorted smem ----
    {
        const unsigned lt = (1u << lane) - 1u;
        int u0 = 0, u1 = 0, u2 = 0, u3 = 0;
        for (int it = 0; it < 8; ++it) {
            int e  = w * 256 + it * 32 + lane;
            int sp = ssp[e];
            unsigned m0 = __ballot_sync(full, sp == 0);
            unsigned m1 = __ballot_sync(full, sp == 1);
            unsigned m2 = __ballot_sync(full, sp == 2);
            unsigned m3 = __ballot_sync(full, sp == 3);
            int pos = -1;
            if (sp == 0)      pos = woff[w][0] + u0 + __popc(m0 & lt);
            else if (sp == 1) pos = woff[w][1] + u1 + __popc(m1 & lt);
            else if (sp == 2) pos = woff[w][2] + u2 + __popc(m2 & lt);
            else if (sp == 3) pos = woff[w][3] + u3 + __popc(m3 & lt);
            if (pos >= 0) {
                const float* cp = coords + (size_t)(b * NN + e) * 3;
                sco[pos] = make_float4(cp[0], cp[1], cp[2], 0.f);
            }
            u0 += __popc(m0); u1 += __popc(m1); u2 += __popc(m2); u3 += __popc(m3);
        }
    }
    __syncthreads();

    // =================== main compute: one warp per row ===================
    const int i = ((blockIdx.x & 255) << 2) + w;
    const float* cc = coords + (size_t)(b * NN + i) * 3;
    const float xi = cc[0], yi = cc[1], zi = cc[2];

    float* orow = out + (size_t)(b * NN + i) * OUTW;
    float4* o4 = (float4*)orow;
    const float4 z4 = make_float4(0.f, 0.f, 0.f, 0.f);
    for (int c = 16 + lane; c < 252; c += 32) o4[c] = z4;   // zero tail

    int sb[5];
#pragma unroll
    for (int k = 0; k < 5; ++k) sb[k] = sbase[k];

    const float T1  = exp2f(ET1);
    const float T4  = exp2f(ET4);
    const float T9  = exp2f(ET9);
    const float T16 = exp2f(ET16);
    const float iT16 = exp2f(-ET16);
    const int b0 = lane & 1, b1 = (lane >> 1) & 1, b2 = (lane >> 2) & 1,
              b3 = (lane >> 3) & 1;

#pragma unroll
    for (int s = 0; s < 4; ++s) {
        float acc[16];
#pragma unroll
        for (int k = 0; k < 16; ++k) acc[k] = 0.f;

        const int en = sb[s + 1];
        for (int t = sb[s] + lane; t < en; t += 32) {
            float4 cj = sco[t];
            float dx = xi - cj.x, dy = yi - cj.y, dz = zi - cj.z;
            float d2 = fmaf(dx, dx, fmaf(dy, dy, dz * dz));
            bool ok = (d2 > 0.f) && (d2 <= RC2);
            float d  = d2 * rsqrtf(d2);            // NaN at d2==0
            float dm = fminf(d, RCF);              // NaN -> 5.2, far -> 5.2
            float fcv = fmaf(0.5f, __cosf(dm * PI_OVER_RC), 0.5f);
            float fc = ok ? fcv : 0.f;             // exact masking

            float fa = dm - SA;
            float ga = exp2f((-LLCF * fa) * fa);
            float fb = dm - SB;
            float gb = exp2f((-LLCF * fb) * fb);
            float pa = exp2f(fmaf(KPF, dm, -KPF * SA));  // step-up factor @A
            float qa = exp2f(fmaf(-KPF, dm, KPF * SA));  // step-down factor @A
            float pb = pa * T16;                         // step-up @B
            float qb = qa * iT16;                        // step-down @B
            float hA = fc * ga;
            float hB = fc * gb;

            acc[3]  += hA;
            acc[11] += hB;
            float h;
            h = hA * pa; acc[4]  = fmaf(h, T1,  acc[4]);
            h *= pa;     acc[5]  = fmaf(h, T4,  acc[5]);
            h *= pa;     acc[6]  = fmaf(h, T9,  acc[6]);
            h *= pa;     acc[7]  = fmaf(h, T16, acc[7]);
            h = hA * qa; acc[2]  = fmaf(h, T1,  acc[2]);
            h *= qa;     acc[1]  = fmaf(h, T4,  acc[1]);
            h *= qa;     acc[0]  = fmaf(h, T9,  acc[0]);
            h = hB * pb; acc[12] = fmaf(h, T1,  acc[12]);
            h *= pb;     acc[13] = fmaf(h, T4,  acc[13]);
            h *= pb;     acc[14] = fmaf(h, T9,  acc[14]);
            h *= pb;     acc[15] = fmaf(h, T16, acc[15]);
            h = hB * qb; acc[10] = fmaf(h, T1,  acc[10]);
            h *= qb;     acc[9]  = fmaf(h, T4,  acc[9]);
            h *= qb;     acc[8]  = fmaf(h, T9,  acc[8]);
        }

        // ---- shell-distributing butterfly reduction ----
        // round xor 1: keep shells with parity == b0
        float v[8];
#pragma unroll
        for (int j = 0; j < 8; ++j) {
            float snd = b0 ? acc[2 * j] : acc[2 * j + 1];
            float rcv = __shfl_xor_sync(full, snd, 1);
            v[j] = (b0 ? acc[2 * j + 1] : acc[2 * j]) + rcv;
        }
        // round xor 2
        float vv[4];
#pragma unroll
        for (int j = 0; j < 4; ++j) {
            float snd = b1 ? v[2 * j] : v[2 * j + 1];
            float rcv = __shfl_xor_sync(full, snd, 2);
            vv[j] = (b1 ? v[2 * j + 1] : v[2 * j]) + rcv;
        }
        // round xor 4
        float x0, x1;
        {
            float snd = b2 ? vv[0] : vv[1];
            float rcv = __shfl_xor_sync(full, snd, 4);
            x0 = (b2 ? vv[1] : vv[0]) + rcv;
            snd = b2 ? vv[2] : vv[3];
            rcv = __shfl_xor_sync(full, snd, 4);
            x1 = (b2 ? vv[3] : vv[2]) + rcv;
        }
        // round xor 8
        float y;
        {
            float snd = b3 ? x0 : x1;
            float rcv = __shfl_xor_sync(full, snd, 8);
            y = (b3 ? x1 : x0) + rcv;
        }
        // round xor 16: combine lane halves
        y += __shfl_xor_sync(full, y, 16);

        // lane L (<16) now holds total for shell L
        if (lane < 16) orow[s * 16 + lane] = y;
    }
}

extern "C" void kernel_launch(void* const* d_in, const int* in_sizes, int n_in,
                              void* d_out, int out_size) {
    (void)in_sizes; (void)n_in; (void)out_size;
    const int*   spec   = (const int*)d_in[0];
    const float* coords = (const float*)d_in[1];
    float*       out    = (float*)d_out;

    aev_fused<<<NB * (NN / 4), 128>>>(spec, coords, out);
}